// round 8
// baseline (speedup 1.0000x reference)
#include <cuda_runtime.h>
#include <cuda_bf16.h>
#include <math.h>
#include <stdint.h>

// Problem constants
#define DIMV   1024
#define NHEADS 16
#define BLKSZ  129
#define DKV    64
#define NBLK   32
#define BATCH  4
#define NLEN   (BLKSZ * NBLK)        // 4128
#define MROWS  (BATCH * NLEN)        // 16512
#define WSZ    (1024 * 1024)

// Scratch (device globals; no allocation allowed)
__device__ float g_q[MROWS * DIMV];
__device__ float g_k[MROWS * DIMV];
__device__ float g_v[MROWS * DIMV];
// bf16 hi/lo split buffers
__device__ __nv_bfloat16 g_xh[MROWS * DIMV];
__device__ __nv_bfloat16 g_xl[MROWS * DIMV];
__device__ __nv_bfloat16 g_aoh[MROWS * DIMV];
__device__ __nv_bfloat16 g_aol[MROWS * DIMV];
__device__ __nv_bfloat16 g_wh[4 * WSZ];   // Wq,Wk,Wv,Wo hi
__device__ __nv_bfloat16 g_wl[4 * WSZ];   // Wq,Wk,Wv,Wo lo

// ---------------------------------------------------------------------------
// helpers
// ---------------------------------------------------------------------------
__device__ __forceinline__ uint32_t smem_u32(const void* p) {
    uint32_t a;
    asm("{ .reg .u64 t; cvta.to.shared.u64 t, %1; cvt.u32.u64 %0, t; }"
        : "=r"(a) : "l"(p));
    return a;
}

__device__ __forceinline__ void cp16(uint32_t s, const void* g) {
    asm volatile("cp.async.cg.shared.global [%0], [%1], 16;" :: "r"(s), "l"(g));
}
#define CP_COMMIT() asm volatile("cp.async.commit_group;" ::: "memory")
#define CP_WAIT1()  asm volatile("cp.async.wait_group 1;" ::: "memory")

// SW64 swizzle (atom: 8 rows x 64B)
__device__ __forceinline__ uint32_t swz64(uint32_t off) {
    return off ^ ((off >> 3) & 0x30);
}

__device__ __forceinline__ void ldsm4(uint32_t* r, uint32_t addr) {
    asm volatile("ldmatrix.sync.aligned.m8n8.x4.shared.b16 {%0,%1,%2,%3}, [%4];"
                 : "=r"(r[0]), "=r"(r[1]), "=r"(r[2]), "=r"(r[3]) : "r"(addr));
}

__device__ __forceinline__ void mma16816(float* d, const uint32_t* a, const uint32_t* b) {
    asm volatile(
        "mma.sync.aligned.m16n8k16.row.col.f32.bf16.bf16.f32 "
        "{%0,%1,%2,%3}, {%4,%5,%6,%7}, {%8,%9}, {%0,%1,%2,%3};"
        : "+f"(d[0]), "+f"(d[1]), "+f"(d[2]), "+f"(d[3])
        : "r"(a[0]), "r"(a[1]), "r"(a[2]), "r"(a[3]), "r"(b[0]), "r"(b[1]));
}

// packed f32x2 (Blackwell FFMA2 path — ptxas never auto-fuses; PTX only)
__device__ __forceinline__ void fma2(uint64_t& d, uint64_t a, uint64_t b) {
    asm("fma.rn.f32x2 %0, %1, %2, %3;" : "=l"(d) : "l"(a), "l"(b), "l"(d));
}
__device__ __forceinline__ uint64_t add2(uint64_t a, uint64_t b) {
    uint64_t r;
    asm("add.rn.f32x2 %0, %1, %2;" : "=l"(r) : "l"(a), "l"(b));
    return r;
}
__device__ __forceinline__ void unpack2(uint64_t v, float& x, float& y) {
    asm("mov.b64 {%0, %1}, %2;" : "=f"(x), "=f"(y) : "l"(v));
}
__device__ __forceinline__ uint64_t bcast2(float x) {
    uint64_t r;
    asm("mov.b64 %0, {%1, %1};" : "=l"(r) : "f"(x));
    return r;
}

// ---------------------------------------------------------------------------
// fp32 -> (hi, lo) bf16 splits
// ---------------------------------------------------------------------------
__device__ __forceinline__ void split1(float v, __nv_bfloat16& h, __nv_bfloat16& l) {
    h = __float2bfloat16(v);
    l = __float2bfloat16(v - __bfloat162float(h));
}

__global__ void split_bf16_kernel(const float* __restrict__ src,
                                  __nv_bfloat16* __restrict__ hi,
                                  __nv_bfloat16* __restrict__ lo, int n4) {
    int i = blockIdx.x * blockDim.x + threadIdx.x;
    if (i >= n4) return;
    float4 v = ((const float4*)src)[i];
    __nv_bfloat16 h0, h1, h2, h3, l0, l1, l2, l3;
    split1(v.x, h0, l0); split1(v.y, h1, l1);
    split1(v.z, h2, l2); split1(v.w, h3, l3);
    ((__nv_bfloat162*)hi)[2 * i + 0] = __nv_bfloat162(h0, h1);
    ((__nv_bfloat162*)hi)[2 * i + 1] = __nv_bfloat162(h2, h3);
    ((__nv_bfloat162*)lo)[2 * i + 0] = __nv_bfloat162(l0, l1);
    ((__nv_bfloat162*)lo)[2 * i + 1] = __nv_bfloat162(l2, l3);
}

// all 4 weights in one launch; 1024 blocks per weight
__global__ void split_w4_kernel(const float* __restrict__ s0, const float* __restrict__ s1,
                                const float* __restrict__ s2, const float* __restrict__ s3,
                                __nv_bfloat16* __restrict__ hi, __nv_bfloat16* __restrict__ lo) {
    int w = blockIdx.x >> 10;
    int i = (blockIdx.x & 1023) * 256 + threadIdx.x;     // < 262144
    const float* src = (w == 0) ? s0 : (w == 1) ? s1 : (w == 2) ? s2 : s3;
    float4 v = ((const float4*)src)[i];
    __nv_bfloat16 h0, h1, h2, h3, l0, l1, l2, l3;
    split1(v.x, h0, l0); split1(v.y, h1, l1);
    split1(v.z, h2, l2); split1(v.w, h3, l3);
    __nv_bfloat16* hp = hi + (size_t)w * WSZ;
    __nv_bfloat16* lp = lo + (size_t)w * WSZ;
    ((__nv_bfloat162*)hp)[2 * i + 0] = __nv_bfloat162(h0, h1);
    ((__nv_bfloat162*)hp)[2 * i + 1] = __nv_bfloat162(h2, h3);
    ((__nv_bfloat162*)lp)[2 * i + 0] = __nv_bfloat162(l0, l1);
    ((__nv_bfloat162*)lp)[2 * i + 1] = __nv_bfloat162(l2, l3);
}

// ---------------------------------------------------------------------------
// HMMA bf16-split GEMM, fused over several weight matrices.
// C_sel[M,1024] = A[M,1024] * B_sel[1024,1024]^T (+bias), sel = blockIdx.x/8
// CTA tile 128x128, BK=32, 8 warps (4x2), 3-stage cp.async, 2 CTAs/SM.
// ---------------------------------------------------------------------------
#define GM_BK 32
#define NSTAGE 3
#define STG_A_HI 0
#define STG_A_LO 8192
#define STG_B_HI 16384
#define STG_B_LO 24576
#define STG_BYTES 32768
#define GEMM_SMEM (NSTAGE * STG_BYTES)     // 98304
#define NCHUNK 32

__global__ __launch_bounds__(256, 2)
void gemm_tc(const __nv_bfloat16* __restrict__ Ahi, const __nv_bfloat16* __restrict__ Alo,
             const __nv_bfloat16* __restrict__ Bhi, const __nv_bfloat16* __restrict__ Blo,
             float* o0, float* o1, float* o2,
             const float* __restrict__ bias)
{
    extern __shared__ char smem[];
    const uint32_t sb = smem_u32(smem);
    const int tid  = threadIdx.x;
    const int wid  = tid >> 5;
    const int lane = tid & 31;
    const int warp_m = wid >> 1;
    const int warp_n = wid & 1;
    const int sel  = blockIdx.x >> 3;
    const int brow = blockIdx.y * 128;
    const int bcol = (blockIdx.x & 7) * 128;

    const __nv_bfloat16* Bh = Bhi + (size_t)sel * WSZ;
    const __nv_bfloat16* Bl = Blo + (size_t)sel * WSZ;
    float* C = (sel == 0) ? o0 : (sel == 1) ? o1 : o2;

    const int lr0 = tid >> 1;
    const int ls0 = (tid & 1) * 2;

    auto load_stage = [&](int c) {
        const uint32_t st = sb + (c % NSTAGE) * STG_BYTES;
        const int k0 = c * GM_BK;
        #pragma unroll
        for (int i = 0; i < 2; i++) {
            int s = ls0 + i;
            uint32_t so = swz64((uint32_t)(lr0 * 64 + s * 16));
            size_t ga = (size_t)(brow + lr0) * 1024 + k0 + s * 8;
            size_t gb = (size_t)(bcol + lr0) * 1024 + k0 + s * 8;
            cp16(st + STG_A_HI + so, Ahi + ga);
            cp16(st + STG_A_LO + so, Alo + ga);
            cp16(st + STG_B_HI + so, Bh + gb);
            cp16(st + STG_B_LO + so, Bl + gb);
        }
        CP_COMMIT();
    };

    float acc[2][8][4];
    #pragma unroll
    for (int i = 0; i < 2; i++)
        #pragma unroll
        for (int j = 0; j < 8; j++)
            #pragma unroll
            for (int q = 0; q < 4; q++) acc[i][j][q] = 0.f;

    load_stage(0);
    load_stage(1);

    const int a_row_l = (lane & 15);
    const int a_kb_l  = (lane >> 4) * 16;
    const int b_row_l = ((lane >> 4) * 8) + (lane & 7);
    const int b_kb_l  = ((lane >> 3) & 1) * 16;

    #pragma unroll 1
    for (int c = 0; c < NCHUNK; c++) {
        CP_WAIT1();
        __syncthreads();
        if (c + 2 < NCHUNK) load_stage(c + 2);
        else CP_COMMIT();

        const uint32_t st = sb + (c % NSTAGE) * STG_BYTES;

        #pragma unroll
        for (int ks = 0; ks < 2; ks++) {
            uint32_t ah[2][4], al[2][4];
            #pragma unroll
            for (int mf = 0; mf < 2; mf++) {
                int row = warp_m * 32 + mf * 16 + a_row_l;
                uint32_t off = swz64((uint32_t)(row * 64 + ks * 32 + a_kb_l));
                ldsm4(ah[mf], st + STG_A_HI + off);
                ldsm4(al[mf], st + STG_A_LO + off);
            }
            #pragma unroll
            for (int g = 0; g < 4; g++) {
                int row = warp_n * 64 + g * 16 + b_row_l;
                uint32_t off = swz64((uint32_t)(row * 64 + ks * 32 + b_kb_l));
                uint32_t bh[4], bl[4];
                ldsm4(bh, st + STG_B_HI + off);
                ldsm4(bl, st + STG_B_LO + off);
                #pragma unroll
                for (int mf = 0; mf < 2; mf++)
                    #pragma unroll
                    for (int h = 0; h < 2; h++) {
                        float* d = acc[mf][g * 2 + h];
                        mma16816(d, ah[mf], &bh[h * 2]);   // hi*hi
                        mma16816(d, ah[mf], &bl[h * 2]);   // hi*lo
                        mma16816(d, al[mf], &bh[h * 2]);   // lo*hi
                    }
            }
        }
    }

    // epilogue
    #pragma unroll
    for (int mf = 0; mf < 2; mf++) {
        int r0 = brow + warp_m * 32 + mf * 16 + (lane >> 2);
        #pragma unroll
        for (int nf = 0; nf < 8; nf++) {
            int col = bcol + warp_n * 64 + nf * 8 + (lane & 3) * 2;
            float b0 = 0.f, b1 = 0.f;
            if (bias) { b0 = bias[col]; b1 = bias[col + 1]; }
            float2 v0 = make_float2(acc[mf][nf][0] + b0, acc[mf][nf][1] + b1);
            float2 v1 = make_float2(acc[mf][nf][2] + b0, acc[mf][nf][3] + b1);
            *(float2*)&C[(size_t)r0 * 1024 + col]       = v0;
            *(float2*)&C[(size_t)(r0 + 8) * 1024 + col] = v1;
        }
    }
}

// ---------------------------------------------------------------------------
// Per-block attention, single pass, packed f32x2 math (FFMA2).
// One CTA per (b, blk, head), 128 threads. Softmax via shift-invariant bound
// m_hat = scale*|q|*max_k|k| (Cauchy-Schwarz) -> no max scan, no score store.
// K and V staged in smem (67KB -> 3 CTAs/SM). Thread t owns query t (t<128);
// query 128 handled cooperatively. Writes hi/lo bf16 split directly.
// ---------------------------------------------------------------------------
#define ATT_SMEM ((2 * BLKSZ * DKV + 64 + BLKSZ + 8 + 3) * (int)sizeof(float))

__global__ __launch_bounds__(128, 3)
void attn_block_kernel()
{
    const int h = blockIdx.x % NHEADS;
    const int j = (blockIdx.x / NHEADS) % NBLK;
    const int b = blockIdx.x / (NHEADS * NBLK);

    extern __shared__ float sm[];
    float* Ks   = sm;                        // 129*64
    float* Vs   = sm + BLKSZ * DKV;          // 129*64
    float* q128 = sm + 2 * BLKSZ * DKV;      // 64
    float* ps   = q128 + 64;                 // 129
    float* red  = ps + BLKSZ;                // warp maxes

    const size_t base = ((size_t)b * NLEN + (size_t)j * BLKSZ) * DIMV + h * DKV;
    const int t = threadIdx.x;               // 0..127
    const float scale = 0.125f;              // 1/sqrt(64)

    // stage K and V (129 rows x 64 floats each)
    for (int idx = t; idx < BLKSZ * (DKV / 4); idx += 128) {
        int r  = idx / (DKV / 4);
        int c4 = (idx % (DKV / 4)) * 4;
        *(float4*)&Ks[r * DKV + c4] = *(const float4*)&g_k[base + (size_t)r * DIMV + c4];
        *(float4*)&Vs[r * DKV + c4] = *(const float4*)&g_v[base + (size_t)r * DIMV + c4];
    }
    if (t < 16)
        *(float4*)&q128[t * 4] = *(const float4*)&g_q[base + (size_t)128 * DIMV + t * 4];
    __syncthreads();

    // max_k |k|^2 (thread t -> row t; thread 0 also row 128)
    {
        float k2 = 0.f;
        #pragma unroll
        for (int d4 = 0; d4 < DKV / 4; d4++) {
            float4 kv = *(const float4*)&Ks[t * DKV + d4 * 4];
            k2 += kv.x * kv.x + kv.y * kv.y + kv.z * kv.z + kv.w * kv.w;
        }
        if (t == 0) {
            float e2 = 0.f;
            #pragma unroll
            for (int d4 = 0; d4 < DKV / 4; d4++) {
                float4 kv = *(const float4*)&Ks[128 * DKV + d4 * 4];
                e2 += kv.x * kv.x + kv.y * kv.y + kv.z * kv.z + kv.w * kv.w;
            }
            k2 = fmaxf(k2, e2);
        }
        #pragma unroll
        for (int o = 16; o > 0; o >>= 1)
            k2 = fmaxf(k2, __shfl_xor_sync(0xffffffffu, k2, o));
        if ((t & 31) == 0) red[t >> 5] = k2;
    }
    __syncthreads();
    const float maxk2 = fmaxf(fmaxf(red[0], red[1]), fmaxf(red[2], red[3]));

    // ---- main: query t (packed f32x2 registers) ----
    uint64_t q2[DKV / 2];       // dims (2i, 2i+1)
    {
        const ulonglong2* qp = (const ulonglong2*)&g_q[base + (size_t)t * DIMV];
        #pragma unroll
        for (int i = 0; i < DKV / 4; i++) {
            ulonglong2 qv = qp[i];
            q2[2 * i] = qv.x;
            q2[2 * i + 1] = qv.y;
        }
    }
    float q2n;
    {
        uint64_t nn = 0;
        #pragma unroll
        for (int i = 0; i < DKV / 2; i++) fma2(nn, q2[i], q2[i]);
        float a, bq;
        unpack2(nn, a, bq);
        q2n = a + bq;
    }
    const float mhat = scale * sqrtf(q2n * maxk2);   // >= every score for this query

    float l = 0.f;
    uint64_t acc2[DKV / 2];
    #pragma unroll
    for (int i = 0; i < DKV / 2; i++) acc2[i] = 0;

    #pragma unroll 1
    for (int kk = 0; kk < BLKSZ; kk++) {
        const ulonglong2* kr = (const ulonglong2*)&Ks[kk * DKV];
        uint64_t d0 = 0, d1 = 0, d2 = 0, d3 = 0;
        #pragma unroll
        for (int i = 0; i < DKV / 8; i++) {          // 8 iterations
            ulonglong2 ka = kr[2 * i];
            ulonglong2 kb = kr[2 * i + 1];
            fma2(d0, q2[4 * i + 0], ka.x);
            fma2(d1, q2[4 * i + 1], ka.y);
            fma2(d2, q2[4 * i + 2], kb.x);
            fma2(d3, q2[4 * i + 3], kb.y);
        }
        float sa, sb_;
        unpack2(add2(add2(d0, d2), add2(d1, d3)), sa, sb_);
        const float p = __expf(scale * (sa + sb_) - mhat);
        l += p;
        const uint64_t pp = bcast2(p);
        const ulonglong2* vr = (const ulonglong2*)&Vs[kk * DKV];
        #pragma unroll
        for (int i = 0; i < DKV / 4; i++) {
            ulonglong2 vv = vr[i];
            fma2(acc2[2 * i + 0], vv.x, pp);
            fma2(acc2[2 * i + 1], vv.y, pp);
        }
    }
    {
        const float inv = 1.f / l;
        const size_t ob = base + (size_t)t * DIMV;
        #pragma unroll
        for (int i = 0; i < DKV / 2; i++) {
            float v0, v1;
            unpack2(acc2[i], v0, v1);
            v0 *= inv; v1 *= inv;
            __nv_bfloat16 h0, h1, l0, l1;
            split1(v0, h0, l0); split1(v1, h1, l1);
            *(__nv_bfloat162*)&g_aoh[ob + 2 * i] = __nv_bfloat162(h0, h1);
            *(__nv_bfloat162*)&g_aol[ob + 2 * i] = __nv_bfloat162(l0, l1);
        }
    }

    // ---- cooperative tail: query 128 ----
    {
        float e2 = 0.f;
        #pragma unroll
        for (int d4 = 0; d4 < DKV / 4; d4++) {
            float4 qv = *(const float4*)&q128[d4 * 4];
            e2 += qv.x * qv.x + qv.y * qv.y + qv.z * qv.z + qv.w * qv.w;
        }
        const float mh8 = scale * sqrtf(e2 * maxk2);

        for (int kk = t; kk < BLKSZ; kk += 128) {
            const float* kr = &Ks[kk * DKV];
            float s0 = 0.f, s1 = 0.f, s2 = 0.f, s3 = 0.f;
            #pragma unroll
            for (int d4 = 0; d4 < DKV / 4; d4++) {
                float4 kv = *(const float4*)&kr[d4 * 4];
                float4 qv = *(const float4*)&q128[d4 * 4];
                s0 += qv.x * kv.x; s1 += qv.y * kv.y;
                s2 += qv.z * kv.z; s3 += qv.w * kv.w;
            }
            ps[kk] = __expf(scale * ((s0 + s1) + (s2 + s3)) - mh8);
        }
        __syncthreads();

        if (t < DKV) {
            float a = 0.f, lsum = 0.f;
            #pragma unroll 1
            for (int kk = 0; kk < BLKSZ; kk++) {
                float p = ps[kk];
                lsum += p;
                a += p * Vs[kk * DKV + t];
            }
            float v = a / lsum;
            __nv_bfloat16 hh, ll;
            split1(v, hh, ll);
            const size_t ob = base + (size_t)128 * DIMV + t;
            g_aoh[ob] = hh;
            g_aol[ob] = ll;
        }
    }
}

// ---------------------------------------------------------------------------
// Global attention over the 32 block-leader tokens (added into token 0).
// Reads/updates the hi/lo split representation.
// ---------------------------------------------------------------------------
__global__ void attn_global_kernel()
{
    const int h = blockIdx.x % NHEADS;
    const int b = blockIdx.x / NHEADS;
    const int t = threadIdx.x;           // query block index 0..31

    const size_t hb    = (size_t)h * DKV;
    const size_t qbase = ((size_t)b * NLEN + (size_t)t * BLKSZ) * DIMV + hb;

    float qr[DKV];
    #pragma unroll
    for (int d = 0; d < DKV; d++) qr[d] = g_q[qbase + d];

    const float scale = 0.125f;
    float sc[NBLK];
    float mx = -1e30f;
    for (int kk = 0; kk < NBLK; kk++) {
        const size_t kbase = ((size_t)b * NLEN + (size_t)kk * BLKSZ) * DIMV + hb;
        float s0 = 0.f, s1 = 0.f, s2 = 0.f, s3 = 0.f;
        #pragma unroll
        for (int d = 0; d < DKV; d += 4) {
            s0 += qr[d + 0] * g_k[kbase + d + 0];
            s1 += qr[d + 1] * g_k[kbase + d + 1];
            s2 += qr[d + 2] * g_k[kbase + d + 2];
            s3 += qr[d + 3] * g_k[kbase + d + 3];
        }
        float s = scale * ((s0 + s1) + (s2 + s3));
        sc[kk] = s;
        mx = fmaxf(mx, s);
    }
    float l = 0.f;
    for (int kk = 0; kk < NBLK; kk++) {
        float p = __expf(sc[kk] - mx);
        sc[kk] = p;
        l += p;
    }
    const float inv = 1.f / l;

    float acc[DKV];
    #pragma unroll
    for (int d = 0; d < DKV; d++) acc[d] = 0.f;
    for (int kk = 0; kk < NBLK; kk++) {
        const size_t vbase = ((size_t)b * NLEN + (size_t)kk * BLKSZ) * DIMV + hb;
        float p = sc[kk];
        #pragma unroll
        for (int d = 0; d < DKV; d++) acc[d] += p * g_v[vbase + d];
    }
    #pragma unroll
    for (int d = 0; d < DKV; d++) {
        float cur = __bfloat162float(g_aoh[qbase + d]) + __bfloat162float(g_aol[qbase + d]);
        float nv  = cur + acc[d] * inv;
        __nv_bfloat16 hh, ll;
        split1(nv, hh, ll);
        g_aoh[qbase + d] = hh;
        g_aol[qbase + d] = ll;
    }
}

// ---------------------------------------------------------------------------
// launcher
// ---------------------------------------------------------------------------
extern "C" void kernel_launch(void* const* d_in, const int* in_sizes, int n_in,
                              void* d_out, int out_size)
{
    const float* x  = (const float*)d_in[0];
    const float* Wq = (const float*)d_in[1];
    const float* Wk = (const float*)d_in[2];
    const float* Wv = (const float*)d_in[3];
    const float* Wo = (const float*)d_in[4];
    const float* bo = (const float*)d_in[5];
    float* out = (float*)d_out;

    float *qp, *kp, *vp;
    cudaGetSymbolAddress((void**)&qp,  g_q);
    cudaGetSymbolAddress((void**)&kp,  g_k);
    cudaGetSymbolAddress((void**)&vp,  g_v);
    __nv_bfloat16 *xh, *xl, *aoh, *aol, *wh, *wl;
    cudaGetSymbolAddress((void**)&xh,  g_xh);
    cudaGetSymbolAddress((void**)&xl,  g_xl);
    cudaGetSymbolAddress((void**)&aoh, g_aoh);
    cudaGetSymbolAddress((void**)&aol, g_aol);
    cudaGetSymbolAddress((void**)&wh,  g_wh);
    cudaGetSymbolAddress((void**)&wl,  g_wl);

    cudaFuncSetAttribute(gemm_tc,
                         cudaFuncAttributeMaxDynamicSharedMemorySize, GEMM_SMEM);
    cudaFuncSetAttribute(attn_block_kernel,
                         cudaFuncAttributeMaxDynamicSharedMemorySize, ATT_SMEM);

    // launch 0: all weight splits
    split_w4_kernel<<<4096, 256>>>(Wq, Wk, Wv, Wo, wh, wl);
    // launch 1: x split
    {
        int n4 = MROWS * DIMV / 4;
        split_bf16_kernel<<<(n4 + 255) / 256, 256>>>(x, xh, xl, n4);
    }
    // launch 2: fused QKV projection
    gemm_tc<<<dim3(24, MROWS / 128), 256, GEMM_SMEM>>>(
        xh, xl, wh, wl, qp, kp, vp, nullptr);
    // launch 3: per-block attention (single-pass, f32x2, writes hi/lo split)
    attn_block_kernel<<<BATCH * NBLK * NHEADS, 128, ATT_SMEM>>>();
    // launch 4: global leader-token attention (updates split)
    attn_global_kernel<<<BATCH * NHEADS, 32>>>();
    // launch 5: output projection + bias
    gemm_tc<<<dim3(8, MROWS / 128), 256, GEMM_SMEM>>>(
        aoh, aol, wh + 3 * (size_t)WSZ, wl + 3 * (size_t)WSZ, out, out, out, bo);
}